// round 1
// baseline (speedup 1.0000x reference)
#include <cuda_runtime.h>
#include <cstdint>

// Problem constants
// x:      (16, 16, 64, 512)  f32   -> 8,388,608 elems
// kernel: (32, 16, 4)        f32   -> 2,048 elems
// points: (16, 3, 64, 512)   f32   -> 1,572,864 elems
// out:    (16, 32, 62, 510)  f32   -> 10,137,600 elems
#define CH_STRIDE 32768   // 64*512
#define HP 62
#define WP 510
#define OUT_PLANE (62*510)

typedef unsigned long long u64;

__device__ __forceinline__ u64 pk(float lo, float hi) {
    u64 r; asm("mov.b64 %0, {%1,%2};" : "=l"(r) : "f"(lo), "f"(hi)); return r;
}
__device__ __forceinline__ void upk(u64 v, float& lo, float& hi) {
    asm("mov.b64 {%0,%1}, %2;" : "=f"(lo), "=f"(hi) : "l"(v));
}
__device__ __forceinline__ u64 fma2(u64 a, u64 b, u64 c) {
    u64 d; asm("fma.rn.f32x2 %0, %1, %2, %3;" : "=l"(d) : "l"(a), "l"(b), "l"(c)); return d;
}
__device__ __forceinline__ u64 add2(u64 a, u64 b) {
    u64 d; asm("add.rn.f32x2 %0, %1, %2;" : "=l"(d) : "l"(a), "l"(b)); return d;
}

__global__ void __launch_bounds__(256, 2)
flex_conv_kernel(const float* __restrict__ x,
                 const float* __restrict__ kern,
                 const float* __restrict__ pts,
                 float* __restrict__ out)
{
    // Kernel staged in smem, transposed: Ks[c][o] with c = i*4+d.
    // Stored as ulonglong2 so LDS.128 yields two aligned f32x2 pairs.
    __shared__ ulonglong2 Ks4[64 * 8];
    {
        float* Ksf = reinterpret_cast<float*>(Ks4);
        #pragma unroll
        for (int idx = threadIdx.x; idx < 2048; idx += 256) {
            int c = idx >> 5, o = idx & 31;
            Ksf[idx] = kern[o * 64 + c];   // kernel[o][i][d] flat = o*64 + c
        }
    }
    __syncthreads();

    const int w = blockIdx.x * 256 + threadIdx.x;
    const int h = blockIdx.y;
    const int b = blockIdx.z;
    if (w >= WP) return;

    // A2[pr]  = {A[2pr],   A[2pr+1]}   (box sum of x)
    // Bnd[pr] = {-B[2pr][d], -B[2pr+1][d]}  (negated box sum of pts_d * x)
    u64 A2[8], Bn0[8], Bn1[8], Bn2[8];
    #pragma unroll
    for (int p = 0; p < 8; ++p) { A2[p] = 0ull; Bn0[p] = 0ull; Bn1[p] = 0ull; Bn2[p] = 0ull; }

    const float* xb = x   + ((b * 16) * 64 + h) * 512 + w;
    const float* pb = pts + ((b * 3)  * 64 + h) * 512 + w;

    #pragma unroll
    for (int k = 0; k < 3; ++k) {
        #pragma unroll
        for (int f = 0; f < 3; ++f) {
            const int off = k * 512 + f;
            float p0 = pb[off];
            float p1 = pb[CH_STRIDE + off];
            float p2 = pb[2 * CH_STRIDE + off];
            u64 pn0 = pk(-p0, -p0);
            u64 pn1 = pk(-p1, -p1);
            u64 pn2 = pk(-p2, -p2);
            #pragma unroll
            for (int pr = 0; pr < 8; ++pr) {
                float xa = xb[(2 * pr)     * CH_STRIDE + off];
                float xc = xb[(2 * pr + 1) * CH_STRIDE + off];
                u64 xx = pk(xa, xc);
                A2[pr]  = add2(A2[pr], xx);
                Bn0[pr] = fma2(pn0, xx, Bn0[pr]);
                Bn1[pr] = fma2(pn1, xx, Bn1[pr]);
                Bn2[pr] = fma2(pn2, xx, Bn2[pr]);
            }
        }
    }

    // Window center: points[b, d, h+1, w+1]
    const int coff = 512 + 1;
    u64 cc0 = pk(pb[coff],               pb[coff]);
    u64 cc1 = pk(pb[CH_STRIDE + coff],   pb[CH_STRIDE + coff]);
    u64 cc2 = pk(pb[2*CH_STRIDE + coff], pb[2*CH_STRIDE + coff]);

    // acc[q] = {out[2q], out[2q+1]}, q = 0..15 over 32 output channels
    u64 acc[16];
    #pragma unroll
    for (int q = 0; q < 16; ++q) acc[q] = 0ull;

    #pragma unroll
    for (int pr = 0; pr < 8; ++pr) {
        // C[i][d] = ctr_d * A[i] - B[i][d]  (Bn holds -B, so plain fma)
        u64 C0 = fma2(cc0, A2[pr], Bn0[pr]);
        u64 C1 = fma2(cc1, A2[pr], Bn1[pr]);
        u64 C2 = fma2(cc2, A2[pr], Bn2[pr]);
        float c0l, c0h, c1l, c1h, c2l, c2h, al, ah;
        upk(C0, c0l, c0h); upk(C1, c1l, c1h); upk(C2, c2l, c2h); upk(A2[pr], al, ah);
        const float cs[2][4] = {{c0l, c1l, c2l, al}, {c0h, c1h, c2h, ah}};
        #pragma unroll
        for (int ii = 0; ii < 2; ++ii) {
            const int i = 2 * pr + ii;
            #pragma unroll
            for (int d = 0; d < 4; ++d) {
                const u64 bb = pk(cs[ii][d], cs[ii][d]);
                const ulonglong2* kr = &Ks4[(i * 4 + d) * 8];
                #pragma unroll
                for (int q = 0; q < 8; ++q) {
                    ulonglong2 kk = kr[q];
                    acc[2*q]     = fma2(kk.x, bb, acc[2*q]);
                    acc[2*q + 1] = fma2(kk.y, bb, acc[2*q + 1]);
                }
            }
        }
    }

    float* op = out + ((size_t)(b * 32) * HP + h) * WP + w;
    #pragma unroll
    for (int q = 0; q < 16; ++q) {
        float lo, hi; upk(acc[q], lo, hi);
        op[(size_t)(2*q)     * OUT_PLANE] = lo;
        op[(size_t)(2*q + 1) * OUT_PLANE] = hi;
    }
}

extern "C" void kernel_launch(void* const* d_in, const int* in_sizes, int n_in,
                              void* d_out, int out_size)
{
    // Identify inputs by element count (robust to metadata ordering).
    const float* x = nullptr; const float* kern = nullptr; const float* pts = nullptr;
    for (int i = 0; i < n_in; ++i) {
        if (in_sizes[i] == 8388608)      x    = (const float*)d_in[i];
        else if (in_sizes[i] == 2048)    kern = (const float*)d_in[i];
        else if (in_sizes[i] == 1572864) pts  = (const float*)d_in[i];
    }
    dim3 grid(2, 62, 16);   // ceil(510/256), Hp, B
    flex_conv_kernel<<<grid, 256>>>(x, kern, pts, (float*)d_out);
}

// round 2
// speedup vs baseline: 1.2301x; 1.2301x over previous
#include <cuda_runtime.h>
#include <cstdint>

// x:      (16, 16, 64, 512)  f32
// kernel: (32, 16, 4)        f32
// points: (16, 3, 64, 512)   f32
// out:    (16, 32, 62, 510)  f32
#define CH_STRIDE 32768   // 64*512
#define HP 62
#define WP 510
#define OUT_PLANE (62*510)

typedef unsigned long long u64;

__device__ __forceinline__ u64 pk(float lo, float hi) {
    u64 r; asm("mov.b64 %0, {%1,%2};" : "=l"(r) : "f"(lo), "f"(hi)); return r;
}
__device__ __forceinline__ void upk(u64 v, float& lo, float& hi) {
    asm("mov.b64 {%0,%1}, %2;" : "=f"(lo), "=f"(hi) : "l"(v));
}
__device__ __forceinline__ u64 fma2(u64 a, u64 b, u64 c) {
    u64 d; asm("fma.rn.f32x2 %0, %1, %2, %3;" : "=l"(d) : "l"(a), "l"(b), "l"(c)); return d;
}
__device__ __forceinline__ u64 add2(u64 a, u64 b) {
    u64 d; asm("add.rn.f32x2 %0, %1, %2;" : "=l"(d) : "l"(a), "l"(b)); return d;
}
__device__ __forceinline__ u64 mul2(u64 a, u64 b) {
    u64 d; asm("mul.rn.f32x2 %0, %1, %2;" : "=l"(d) : "l"(a), "l"(b)); return d;
}
__device__ __forceinline__ u64 neg2(u64 a) {
    return a ^ 0x8000000080000000ULL;
}

// Each thread computes TWO output pixels: (h0, w) and (h0+1, w), all 32 out
// channels. The two 3x3 windows share x-rows h0+1..h0+2 and all point loads.
// Weights (8KB in smem) are read once per thread and serve both pixels,
// halving LDS wavefronts per pixel vs R1.
__global__ void __launch_bounds__(128, 2)
flex_conv2_kernel(const float* __restrict__ x,
                  const float* __restrict__ kern,
                  const float* __restrict__ pts,
                  float* __restrict__ out)
{
    // Transposed kernel in smem: Ks[c][o], c = i*4+d, as ulonglong2 rows of 8.
    __shared__ ulonglong2 Ks4[64 * 8];
    {
        float* Ksf = reinterpret_cast<float*>(Ks4);
        #pragma unroll
        for (int t = 0; t < 16; ++t) {
            int idx = t * 128 + threadIdx.x;
            int c = idx >> 5, o = idx & 31;
            Ksf[idx] = kern[o * 64 + c];
        }
    }
    __syncthreads();

    const int w = blockIdx.x * 128 + threadIdx.x;
    if (w >= WP) return;
    const int h0 = blockIdx.y * 2;      // 0..60, handles rows h0 and h0+1
    const int b  = blockIdx.z;

    // Points, packed {v,v} for f32x2 math: rows h0..h0+3, cols w..w+2, d=0..2
    const float* pb = pts + ((size_t)(b * 3) * 64 + h0) * 512 + w;
    u64 pp[4][3][3];
    #pragma unroll
    for (int d = 0; d < 3; ++d)
        #pragma unroll
        for (int r = 0; r < 4; ++r)
            #pragma unroll
            for (int f = 0; f < 3; ++f) {
                float v = pb[d * CH_STRIDE + r * 512 + f];
                pp[r][f][d] = pk(v, v);
            }

    const float* xb = x + ((size_t)(b * 16) * 64 + h0) * 512 + w;

    // acc{0,1}[j] = {out[2j], out[2j+1]} for pixel rows h0 / h0+1
    u64 acc0[16], acc1[16];
    #pragma unroll
    for (int j = 0; j < 16; ++j) { acc0[j] = 0ull; acc1[j] = 0ull; }

    #pragma unroll 1
    for (int pr = 0; pr < 8; ++pr) {
        const float* xc0 = xb + (size_t)(2 * pr) * CH_STRIDE;
        const float* xc1 = xc0 + CH_STRIDE;

        // xx[r][f] = {x[2pr], x[2pr+1]} at (row h0+r, col w+f)
        u64 xx[4][3];
        #pragma unroll
        for (int r = 0; r < 4; ++r)
            #pragma unroll
            for (int f = 0; f < 3; ++f)
                xx[r][f] = pk(xc0[r * 512 + f], xc1[r * 512 + f]);

        // Per-row partial sums
        u64 Rx[4], Rb[3][4];
        #pragma unroll
        for (int r = 0; r < 4; ++r) {
            Rx[r] = add2(add2(xx[r][0], xx[r][1]), xx[r][2]);
            #pragma unroll
            for (int d = 0; d < 3; ++d)
                Rb[d][r] = fma2(pp[r][2][d], xx[r][2],
                            fma2(pp[r][1][d], xx[r][1],
                             mul2(pp[r][0][d], xx[r][0])));
        }

        // Window sums: px0 uses rows 0..2, px1 uses rows 1..3
        u64 A0 = add2(add2(Rx[0], Rx[1]), Rx[2]);
        u64 A1 = add2(add2(Rx[1], Rx[2]), Rx[3]);
        u64 C0[4], C1[4];
        C0[3] = A0; C1[3] = A1;
        #pragma unroll
        for (int d = 0; d < 3; ++d) {
            u64 B0 = add2(add2(Rb[d][0], Rb[d][1]), Rb[d][2]);
            u64 B1 = add2(add2(Rb[d][1], Rb[d][2]), Rb[d][3]);
            // C = ctr*A - B ; centers: px0 -> pp[1][1][d], px1 -> pp[2][1][d]
            C0[d] = fma2(pp[1][1][d], A0, neg2(B0));
            C1[d] = fma2(pp[2][1][d], A1, neg2(B1));
        }

        // Unpack C halves -> per-input-channel scalars, then GEMV for both px
        float c0lo[4], c0hi[4], c1lo[4], c1hi[4];
        #pragma unroll
        for (int d = 0; d < 4; ++d) {
            upk(C0[d], c0lo[d], c0hi[d]);
            upk(C1[d], c1lo[d], c1hi[d]);
        }

        #pragma unroll
        for (int ii = 0; ii < 2; ++ii) {
            const int i = 2 * pr + ii;
            #pragma unroll
            for (int d = 0; d < 4; ++d) {
                float s0 = ii ? c0hi[d] : c0lo[d];
                float s1 = ii ? c1hi[d] : c1lo[d];
                const u64 bb0 = pk(s0, s0);
                const u64 bb1 = pk(s1, s1);
                const ulonglong2* kr = &Ks4[(i * 4 + d) * 8];
                #pragma unroll
                for (int q = 0; q < 8; ++q) {
                    ulonglong2 kk = kr[q];
                    acc0[2*q]     = fma2(kk.x, bb0, acc0[2*q]);
                    acc0[2*q + 1] = fma2(kk.y, bb0, acc0[2*q + 1]);
                    acc1[2*q]     = fma2(kk.x, bb1, acc1[2*q]);
                    acc1[2*q + 1] = fma2(kk.y, bb1, acc1[2*q + 1]);
                }
            }
        }
    }

    // Store both rows, all 32 channels
    float* op = out + ((size_t)(b * 32) * HP + h0) * WP + w;
    #pragma unroll
    for (int j = 0; j < 16; ++j) {
        float lo, hi;
        upk(acc0[j], lo, hi);
        op[(size_t)(2*j)     * OUT_PLANE] = lo;
        op[(size_t)(2*j + 1) * OUT_PLANE] = hi;
        upk(acc1[j], lo, hi);
        op[(size_t)(2*j)     * OUT_PLANE + WP] = lo;
        op[(size_t)(2*j + 1) * OUT_PLANE + WP] = hi;
    }
}

extern "C" void kernel_launch(void* const* d_in, const int* in_sizes, int n_in,
                              void* d_out, int out_size)
{
    const float* x = nullptr; const float* kern = nullptr; const float* pts = nullptr;
    for (int i = 0; i < n_in; ++i) {
        if (in_sizes[i] == 8388608)      x    = (const float*)d_in[i];
        else if (in_sizes[i] == 2048)    kern = (const float*)d_in[i];
        else if (in_sizes[i] == 1572864) pts  = (const float*)d_in[i];
    }
    dim3 grid(4, 31, 16);   // ceil(510/128), 31 h-pairs, batch
    flex_conv2_kernel<<<grid, 128>>>(x, kern, pts, (float*)d_out);
}